// round 1
// baseline (speedup 1.0000x reference)
#include <cuda_runtime.h>
#include <cstdint>

// Problem constants
#define B_   8
#define C_   128
#define CI_  64
#define N_   4096

// ---------------- scratch (device globals; no allocations) ----------------
__device__ float d_thetaT[B_*N_*CI_];  // [b][n][c]
__device__ float d_phi  [B_*CI_*N_];   // [b][c][m]
__device__ float d_gbuf [B_*CI_*N_];   // [b][c][m]
__device__ float d_y    [B_*N_*CI_];   // [b][n][c]
__device__ float d_cmax [B_*N_];       // per-key column max
__device__ float d_cinv [B_*N_];       // 1 / Z[m]

// ---------------- helpers ----------------
__device__ __forceinline__ float f2tf_f(float f) {
    unsigned u;
    asm("cvt.rna.tf32.f32 %0, %1;" : "=r"(u) : "f"(f));
    return __uint_as_float(u);
}

__device__ __forceinline__ void mma8(float* c, const unsigned* a, const unsigned* b) {
    asm volatile(
        "mma.sync.aligned.m16n8k8.row.col.f32.tf32.tf32.f32 "
        "{%0,%1,%2,%3},{%4,%5,%6,%7},{%8,%9},{%0,%1,%2,%3};\n"
        : "+f"(c[0]), "+f"(c[1]), "+f"(c[2]), "+f"(c[3])
        : "r"(a[0]), "r"(a[1]), "r"(a[2]), "r"(a[3]),
          "r"(b[0]), "r"(b[1]));
}

// =====================================================================
// K1: projections. [192x128] stacked weights @ x[128 x (B*N)] (tf32 mma)
//   rows 0-63: g,  64-127: theta (written transposed), 128-191: phi
// grid (3, 256), block 256. smem: As[64][68], Bs[64][132]
// =====================================================================
__global__ void __launch_bounds__(256)
k1_proj(const float* __restrict__ x,
        const float* __restrict__ g_w,  const float* __restrict__ g_b,
        const float* __restrict__ th_w, const float* __restrict__ th_b,
        const float* __restrict__ ph_w, const float* __restrict__ ph_b)
{
    extern __shared__ float sm[];
    float* As = sm;              // 64*68
    float* Bs = sm + 64*68;      // 64*132

    const int tid  = threadIdx.x;
    const int warp = tid >> 5, lane = tid & 31;
    const int g = lane >> 2, q = lane & 3;
    const int wr0 = (warp >> 2) * 32;   // 0 or 32
    const int wc0 = (warp & 3) * 32;    // 0,32,64,96

    const int mtile = blockIdx.x;            // 0:g 1:theta 2:phi
    const int ntot0 = blockIdx.y * 128;
    const int b  = ntot0 >> 12;
    const int n0 = ntot0 & (N_ - 1);

    const float* wsel = (mtile == 0) ? g_w : (mtile == 1 ? th_w : ph_w);
    const float* bsel = (mtile == 0) ? g_b : (mtile == 1 ? th_b : ph_b);

    float acc[2][4][4];
    #pragma unroll
    for (int mi = 0; mi < 2; mi++)
        #pragma unroll
        for (int ni = 0; ni < 4; ni++)
            #pragma unroll
            for (int e = 0; e < 4; e++) acc[mi][ni][e] = 0.f;

    for (int kc = 0; kc < 2; kc++) {
        const int k0 = kc * 64;
        __syncthreads();
        for (int i = tid; i < 64*64; i += 256) {
            int r = i >> 6, k = i & 63;
            As[r*68 + k] = f2tf_f(wsel[r*128 + k0 + k]);
        }
        for (int i = tid; i < 64*128; i += 256) {
            int k = i >> 7, j = i & 127;
            Bs[k*132 + j] = f2tf_f(x[((size_t)b*C_ + (k0 + k)) * N_ + n0 + j]);
        }
        __syncthreads();

        #pragma unroll
        for (int ks = 0; ks < 8; ks++) {
            const int kb = ks * 8;
            unsigned a[2][4], bb[4][2];
            #pragma unroll
            for (int mi = 0; mi < 2; mi++) {
                int rb = wr0 + mi*16;
                a[mi][0] = __float_as_uint(As[(rb + g    )*68 + kb + q    ]);
                a[mi][1] = __float_as_uint(As[(rb + g + 8)*68 + kb + q    ]);
                a[mi][2] = __float_as_uint(As[(rb + g    )*68 + kb + q + 4]);
                a[mi][3] = __float_as_uint(As[(rb + g + 8)*68 + kb + q + 4]);
            }
            #pragma unroll
            for (int ni = 0; ni < 4; ni++) {
                int cb = wc0 + ni*8;
                bb[ni][0] = __float_as_uint(Bs[(kb + q    )*132 + cb + g]);
                bb[ni][1] = __float_as_uint(Bs[(kb + q + 4)*132 + cb + g]);
            }
            #pragma unroll
            for (int mi = 0; mi < 2; mi++)
                #pragma unroll
                for (int ni = 0; ni < 4; ni++)
                    mma8(acc[mi][ni], a[mi], bb[ni]);
        }
    }

    // epilogue: add bias, scatter to the right scratch buffer/layout
    #pragma unroll
    for (int mi = 0; mi < 2; mi++) {
        #pragma unroll
        for (int ni = 0; ni < 4; ni++) {
            #pragma unroll
            for (int e = 0; e < 4; e++) {
                int row = wr0 + mi*16 + g + ((e >> 1) * 8);   // local 0..63
                int col = wc0 + ni*8 + 2*q + (e & 1);
                float v = acc[mi][ni][e] + bsel[row];
                int nglob = n0 + col;
                if (mtile == 0)
                    d_gbuf[((size_t)b*CI_ + row) * N_ + nglob] = v;
                else if (mtile == 1)
                    d_thetaT[((size_t)b*N_ + nglob) * CI_ + row] = v;
                else
                    d_phi[((size_t)b*CI_ + row) * N_ + nglob] = v;
            }
        }
    }
}

// =====================================================================
// K2: per-key (column) softmax stats. Block owns 128 keys, streams all
// 4096 queries in chunks of 64, online max/sum per column.
// grid (32, 8), block 256. smem: phi_s[64][132], th_s[64][68], red[2][128][2]
// =====================================================================
__global__ void __launch_bounds__(256)
k2_stats()
{
    extern __shared__ float sm[];
    float* phi_s = sm;                     // 64*132
    float* th_s  = phi_s + 64*132;         // 64*68
    float* red   = th_s + 64*68;           // 2*128*2

    const int tid  = threadIdx.x;
    const int warp = tid >> 5, lane = tid & 31;
    const int g = lane >> 2, q = lane & 3;
    const int wr = warp >> 2;              // 0..1 (query rows)
    const int wc = warp & 3;               // 0..3 (key cols)

    const int b  = blockIdx.y;
    const int m0 = blockIdx.x * 128;

    // stage phi key-tile once
    for (int i = tid; i < 64*128; i += 256) {
        int c = i >> 7, j = i & 127;
        phi_s[c*132 + j] = f2tf_f(d_phi[((size_t)b*CI_ + c) * N_ + m0 + j]);
    }

    float rmax[8], rsum[8];
    #pragma unroll
    for (int i = 0; i < 8; i++) { rmax[i] = -3.0e38f; rsum[i] = 0.f; }

    for (int ns = 0; ns < 64; ns++) {
        const int nq0 = ns * 64;
        __syncthreads();
        for (int i = tid; i < 64*64; i += 256) {
            int r = i >> 6, c = i & 63;
            th_s[r*68 + c] = f2tf_f(d_thetaT[((size_t)b*N_ + nq0 + r) * CI_ + c]);
        }
        __syncthreads();

        float acc[2][4][4];
        #pragma unroll
        for (int mi = 0; mi < 2; mi++)
            #pragma unroll
            for (int ni = 0; ni < 4; ni++)
                #pragma unroll
                for (int e = 0; e < 4; e++) acc[mi][ni][e] = 0.f;

        #pragma unroll
        for (int ks = 0; ks < 8; ks++) {
            const int kb = ks * 8;
            unsigned a[2][4], bb[4][2];
            #pragma unroll
            for (int mi = 0; mi < 2; mi++) {
                int rb = wr*32 + mi*16;
                a[mi][0] = __float_as_uint(th_s[(rb + g    )*68 + kb + q    ]);
                a[mi][1] = __float_as_uint(th_s[(rb + g + 8)*68 + kb + q    ]);
                a[mi][2] = __float_as_uint(th_s[(rb + g    )*68 + kb + q + 4]);
                a[mi][3] = __float_as_uint(th_s[(rb + g + 8)*68 + kb + q + 4]);
            }
            #pragma unroll
            for (int ni = 0; ni < 4; ni++) {
                int cb = wc*32 + ni*8;
                bb[ni][0] = __float_as_uint(phi_s[(kb + q    )*132 + cb + g]);
                bb[ni][1] = __float_as_uint(phi_s[(kb + q + 4)*132 + cb + g]);
            }
            #pragma unroll
            for (int mi = 0; mi < 2; mi++)
                #pragma unroll
                for (int ni = 0; ni < 4; ni++)
                    mma8(acc[mi][ni], a[mi], bb[ni]);
        }

        // online per-column (key) max & exp-sum
        #pragma unroll
        for (int ni = 0; ni < 4; ni++) {
            #pragma unroll
            for (int jj = 0; jj < 2; jj++) {
                float v0 = acc[0][ni][jj],     v1 = acc[0][ni][jj + 2];
                float v2 = acc[1][ni][jj],     v3 = acc[1][ni][jj + 2];
                float lm = fmaxf(fmaxf(v0, v1), fmaxf(v2, v3));
                #pragma unroll
                for (int o = 4; o < 32; o <<= 1)
                    lm = fmaxf(lm, __shfl_xor_sync(0xffffffffu, lm, o));
                float ls = __expf(v0 - lm) + __expf(v1 - lm)
                         + __expf(v2 - lm) + __expf(v3 - lm);
                #pragma unroll
                for (int o = 4; o < 32; o <<= 1)
                    ls += __shfl_xor_sync(0xffffffffu, ls, o);
                int idx = ni*2 + jj;
                if (lm > rmax[idx]) {
                    rsum[idx] = rsum[idx] * __expf(rmax[idx] - lm) + ls;
                    rmax[idx] = lm;
                } else {
                    rsum[idx] += ls * __expf(lm - rmax[idx]);
                }
            }
        }
    }

    __syncthreads();
    if (g == 0) {   // lanes 0..3 hold replicated column stats
        #pragma unroll
        for (int ni = 0; ni < 4; ni++) {
            #pragma unroll
            for (int jj = 0; jj < 2; jj++) {
                int col = wc*32 + ni*8 + 2*q + jj;
                int idx = ni*2 + jj;
                red[(wr*128 + col)*2 + 0] = rmax[idx];
                red[(wr*128 + col)*2 + 1] = rsum[idx];
            }
        }
    }
    __syncthreads();
    if (tid < 128) {
        float m0v = red[tid*2],         s0 = red[tid*2 + 1];
        float m1v = red[(128+tid)*2],   s1 = red[(128+tid)*2 + 1];
        float nm = fmaxf(m0v, m1v);
        float Z  = s0 * __expf(m0v - nm) + s1 * __expf(m1v - nm);
        d_cmax[b*N_ + m0 + tid] = nm;
        d_cinv[b*N_ + m0 + tid] = 1.0f / Z;
    }
}

// =====================================================================
// K3: y = softmax(f) @ g  (flash-style recompute). Block owns 128 query
// rows, streams keys in chunks of 64: S=theta^T phi -> P=exp(S-mx) ->
// Y += P @ (g*invZ). grid (32, 8), block 256.
// smem: th_s[128][68], phi_s[64][68], g_s[64][65], P_s[128][68], cm[64]
// =====================================================================
__global__ void __launch_bounds__(256)
k3_attn()
{
    extern __shared__ float sm[];
    float* th_s  = sm;                        // 128*68
    float* phi_s = th_s  + 128*68;            // 64*68
    float* g_s   = phi_s + 64*68;             // 64*65
    float* P_s   = g_s   + 64*65;             // 128*68
    float* cm    = P_s   + 128*68;            // 64

    const int tid  = threadIdx.x;
    const int warp = tid >> 5, lane = tid & 31;
    const int g = lane >> 2, q = lane & 3;
    const int wr1 = warp >> 1;     // 0..3 (query rows, GEMM1)
    const int wc1 = warp & 1;      // 0..1 (key cols,  GEMM1)

    const int b  = blockIdx.y;
    const int n0 = blockIdx.x * 128;

    for (int i = tid; i < 128*64; i += 256) {
        int r = i >> 6, c = i & 63;
        th_s[r*68 + c] = f2tf_f(d_thetaT[((size_t)b*N_ + n0 + r) * CI_ + c]);
    }

    float yacc[8][4];
    #pragma unroll
    for (int ni = 0; ni < 8; ni++)
        #pragma unroll
        for (int e = 0; e < 4; e++) yacc[ni][e] = 0.f;

    for (int ms = 0; ms < 64; ms++) {
        const int m0 = ms * 64;
        __syncthreads();
        for (int i = tid; i < 64*64; i += 256) {
            int c = i >> 6, j = i & 63;
            phi_s[c*68 + j] = f2tf_f(d_phi[((size_t)b*CI_ + c) * N_ + m0 + j]);
        }
        for (int i = tid; i < 64*64; i += 256) {
            int c = i >> 6, j = i & 63;
            float v = d_gbuf[((size_t)b*CI_ + c) * N_ + m0 + j] * d_cinv[b*N_ + m0 + j];
            g_s[j*65 + c] = f2tf_f(v);
        }
        if (tid < 64) cm[tid] = d_cmax[b*N_ + m0 + tid];
        __syncthreads();

        // GEMM1: S[128 x 64]
        float acc[2][4][4];
        #pragma unroll
        for (int mi = 0; mi < 2; mi++)
            #pragma unroll
            for (int ni = 0; ni < 4; ni++)
                #pragma unroll
                for (int e = 0; e < 4; e++) acc[mi][ni][e] = 0.f;

        #pragma unroll
        for (int ks = 0; ks < 8; ks++) {
            const int kb = ks * 8;
            unsigned a[2][4], bb[4][2];
            #pragma unroll
            for (int mi = 0; mi < 2; mi++) {
                int rb = wr1*32 + mi*16;
                a[mi][0] = __float_as_uint(th_s[(rb + g    )*68 + kb + q    ]);
                a[mi][1] = __float_as_uint(th_s[(rb + g + 8)*68 + kb + q    ]);
                a[mi][2] = __float_as_uint(th_s[(rb + g    )*68 + kb + q + 4]);
                a[mi][3] = __float_as_uint(th_s[(rb + g + 8)*68 + kb + q + 4]);
            }
            #pragma unroll
            for (int ni = 0; ni < 4; ni++) {
                int cb = wc1*32 + ni*8;
                bb[ni][0] = __float_as_uint(phi_s[(kb + q    )*68 + cb + g]);
                bb[ni][1] = __float_as_uint(phi_s[(kb + q + 4)*68 + cb + g]);
            }
            #pragma unroll
            for (int mi = 0; mi < 2; mi++)
                #pragma unroll
                for (int ni = 0; ni < 4; ni++)
                    mma8(acc[mi][ni], a[mi], bb[ni]);
        }

        // P = exp(S - colmax) -> smem (tf32-rounded)
        #pragma unroll
        for (int mi = 0; mi < 2; mi++) {
            #pragma unroll
            for (int ni = 0; ni < 4; ni++) {
                #pragma unroll
                for (int e = 0; e < 4; e++) {
                    int row = wr1*32 + mi*16 + g + ((e >> 1) * 8);
                    int col = wc1*32 + ni*8 + 2*q + (e & 1);
                    P_s[row*68 + col] = f2tf_f(__expf(acc[mi][ni][e] - cm[col]));
                }
            }
        }
        __syncthreads();

        // GEMM2: Y[128 x 64] += P[128 x 64] @ g'[64 x 64]
        const int rb = warp * 16;
        #pragma unroll
        for (int ks = 0; ks < 8; ks++) {
            const int kb = ks * 8;
            unsigned a[4];
            a[0] = __float_as_uint(P_s[(rb + g    )*68 + kb + q    ]);
            a[1] = __float_as_uint(P_s[(rb + g + 8)*68 + kb + q    ]);
            a[2] = __float_as_uint(P_s[(rb + g    )*68 + kb + q + 4]);
            a[3] = __float_as_uint(P_s[(rb + g + 8)*68 + kb + q + 4]);
            #pragma unroll
            for (int ni = 0; ni < 8; ni++) {
                unsigned bb[2];
                bb[0] = __float_as_uint(g_s[(kb + q    )*65 + ni*8 + g]);
                bb[1] = __float_as_uint(g_s[(kb + q + 4)*65 + ni*8 + g]);
                mma8(yacc[ni], a, bb);
            }
        }
    }

    // write Y
    const int rb = warp * 16;
    #pragma unroll
    for (int ni = 0; ni < 8; ni++) {
        #pragma unroll
        for (int e = 0; e < 4; e++) {
            int row = n0 + rb + g + ((e >> 1) * 8);
            int col = ni*8 + 2*q + (e & 1);
            d_y[((size_t)b*N_ + row) * CI_ + col] = yacc[ni][e];
        }
    }
}

// =====================================================================
// K4: out = W_w @ y^T + W_b + x. grid (2, 32, 8), block 256.
// smem: Ws[64][68], Ys[64][129]
// =====================================================================
__global__ void __launch_bounds__(256)
k4_out(const float* __restrict__ x,
       const float* __restrict__ Ww, const float* __restrict__ Wb,
       float* __restrict__ out)
{
    extern __shared__ float sm[];
    float* Ws = sm;              // 64*68
    float* Ys = sm + 64*68;      // 64*129

    const int tid  = threadIdx.x;
    const int warp = tid >> 5, lane = tid & 31;
    const int g = lane >> 2, q = lane & 3;
    const int wr0 = (warp >> 2) * 32;
    const int wc0 = (warp & 3) * 32;

    const int co0 = blockIdx.x * 64;
    const int n0  = blockIdx.y * 128;
    const int b   = blockIdx.z;

    for (int i = tid; i < 64*64; i += 256) {
        int r = i >> 6, c = i & 63;
        Ws[r*68 + c] = f2tf_f(Ww[(co0 + r)*CI_ + c]);
    }
    for (int i = tid; i < 64*128; i += 256) {
        int j = i >> 6, c = i & 63;
        Ys[c*129 + j] = f2tf_f(d_y[((size_t)b*N_ + n0 + j) * CI_ + c]);
    }
    __syncthreads();

    float acc[2][4][4];
    #pragma unroll
    for (int mi = 0; mi < 2; mi++)
        #pragma unroll
        for (int ni = 0; ni < 4; ni++)
            #pragma unroll
            for (int e = 0; e < 4; e++) acc[mi][ni][e] = 0.f;

    #pragma unroll
    for (int ks = 0; ks < 8; ks++) {
        const int kb = ks * 8;
        unsigned a[2][4], bb[4][2];
        #pragma unroll
        for (int mi = 0; mi < 2; mi++) {
            int rb = wr0 + mi*16;
            a[mi][0] = __float_as_uint(Ws[(rb + g    )*68 + kb + q    ]);
            a[mi][1] = __float_as_uint(Ws[(rb + g + 8)*68 + kb + q    ]);
            a[mi][2] = __float_as_uint(Ws[(rb + g    )*68 + kb + q + 4]);
            a[mi][3] = __float_as_uint(Ws[(rb + g + 8)*68 + kb + q + 4]);
        }
        #pragma unroll
        for (int ni = 0; ni < 4; ni++) {
            int cb = wc0 + ni*8;
            bb[ni][0] = __float_as_uint(Ys[(kb + q    )*129 + cb + g]);
            bb[ni][1] = __float_as_uint(Ys[(kb + q + 4)*129 + cb + g]);
        }
        #pragma unroll
        for (int mi = 0; mi < 2; mi++)
            #pragma unroll
            for (int ni = 0; ni < 4; ni++)
                mma8(acc[mi][ni], a[mi], bb[ni]);
    }

    #pragma unroll
    for (int mi = 0; mi < 2; mi++) {
        #pragma unroll
        for (int ni = 0; ni < 4; ni++) {
            #pragma unroll
            for (int e = 0; e < 4; e++) {
                int row = co0 + wr0 + mi*16 + g + ((e >> 1) * 8);
                int col = n0 + wc0 + ni*8 + 2*q + (e & 1);
                size_t o = ((size_t)b*C_ + row) * N_ + col;
                out[o] = acc[mi][ni][e] + Wb[row] + x[o];
            }
        }
    }
}

// =====================================================================
extern "C" void kernel_launch(void* const* d_in, const int* in_sizes, int n_in,
                              void* d_out, int out_size)
{
    const float* x    = (const float*)d_in[0];
    const float* g_w  = (const float*)d_in[1];
    const float* g_b  = (const float*)d_in[2];
    const float* th_w = (const float*)d_in[3];
    const float* th_b = (const float*)d_in[4];
    const float* ph_w = (const float*)d_in[5];
    const float* ph_b = (const float*)d_in[6];
    const float* Ww   = (const float*)d_in[7];
    const float* Wb   = (const float*)d_in[8];
    float* out = (float*)d_out;

    const int SM1 = (64*68 + 64*132) * 4;                              // 51200
    const int SM2 = (64*132 + 64*68 + 2*128*2) * 4;                    // 53248
    const int SM3 = (128*68 + 64*68 + 64*65 + 128*68 + 64) * 4;        // 103936
    const int SM4 = (64*68 + 64*129) * 4;                              // 50432

    cudaFuncSetAttribute(k1_proj,  cudaFuncAttributeMaxDynamicSharedMemorySize, SM1);
    cudaFuncSetAttribute(k2_stats, cudaFuncAttributeMaxDynamicSharedMemorySize, SM2);
    cudaFuncSetAttribute(k3_attn,  cudaFuncAttributeMaxDynamicSharedMemorySize, SM3);
    cudaFuncSetAttribute(k4_out,   cudaFuncAttributeMaxDynamicSharedMemorySize, SM4);

    k1_proj <<<dim3(3, 256),    256, SM1>>>(x, g_w, g_b, th_w, th_b, ph_w, ph_b);
    k2_stats<<<dim3(32, 8),     256, SM2>>>();
    k3_attn <<<dim3(32, 8),     256, SM3>>>();
    k4_out  <<<dim3(2, 32, 8),  256, SM4>>>(x, Ww, Wb, out);
}